// round 6
// baseline (speedup 1.0000x reference)
#include <cuda_runtime.h>
#include <cstdint>
#include <math.h>
#include <float.h>

// Shapes
#define B_  64
#define C_  256
#define HW_ 4096        // 64*64
#define K_  21
#define BK_ (B_*K_)     // 1344
#define BC_ (B_*C_)     // 16384
#define KC_ (K_*C_)     // 5376
#define NB_ 8           // b-groups for final partial stage

#define PGRID 444       // persistent grid (~3 blocks/SM on 148 SMs)
#define STAGE_FLOATS (2*HW_)           // s1 + s2 per stage = 8192 floats (32 KB)
#define SMEM_BYTES (2*STAGE_FLOATS*4)  // 2 stages = 64 KB

// Scratch (static device arrays — allowed)
__device__ float g_dot[BC_];
__device__ float g_S1[B_*K_*C_];
__device__ float g_S2[B_*K_*C_];
__device__ float g_part1[K_*NB_*C_];
__device__ float g_part2[K_*NB_*C_];

// Rect from keypoint (x,y): [left,right) x [down,upper), truncate after clip.
// Guaranteed 4 <= nh,nw <= 8.
__device__ __forceinline__ int4 make_rect(float x, float y) {
    int4 rc;
    rc.x = (int)fmaxf(x - 4.0f, 0.0f);   // left   (h)
    rc.y = (int)fminf(x + 4.0f, 63.0f);  // right  (h, excl)
    rc.z = (int)fmaxf(y - 4.0f, 0.0f);   // down   (w)
    rc.w = (int)fminf(y + 4.0f, 63.0f);  // upper  (w, excl)
    return rc;
}

// ---- cp.async helpers -----------------------------------------------------
__device__ __forceinline__ void cp_async16(uint32_t saddr, const void* g) {
    asm volatile("cp.async.cg.shared.global [%0], [%1], 16;" :: "r"(saddr), "l"(g));
}
__device__ __forceinline__ void cp_commit() {
    asm volatile("cp.async.commit_group;" ::: "memory");
}
template<int N> __device__ __forceinline__ void cp_wait() {
    asm volatile("cp.async.wait_group %0;" :: "n"(N) : "memory");
}

// ---------------------------------------------------------------------------
// Kernel 1: persistent, double-buffered streaming pass.
// Each block loops over (b,c) slices; cp.async loads slice i+1 while slice i
// is consumed (dot + 42 rect sums). Loads never stop -> DRAM-bound.
// ---------------------------------------------------------------------------
extern __shared__ float sm[];   // [2][8192]: per stage, s1 then s2

__global__ __launch_bounds__(256) void pass1_kernel(const float* __restrict__ f1,
                                                    const float* __restrict__ f2,
                                                    const float* __restrict__ pre1,
                                                    const float* __restrict__ pre2) {
    __shared__ float red[8];
    const int tid  = threadIdx.x;
    const int warp = tid >> 5, lane = tid & 31;
    const int dh = lane >> 3;   // 0..3
    const int dw = lane & 7;    // 0..7
    const uint32_t smem_base = (uint32_t)__cvta_generic_to_shared(sm);

    int cur = 0;
    int s0 = blockIdx.x;

    // prologue: issue first slice
    {
        const float4* p1 = (const float4*)(f1 + (size_t)s0 * HW_);
        const float4* p2 = (const float4*)(f2 + (size_t)s0 * HW_);
        uint32_t d1 = smem_base + tid * 16;
        uint32_t d2 = d1 + HW_ * 4;
        #pragma unroll
        for (int i = 0; i < 4; i++) {
            cp_async16(d1 + i * 256 * 16, p1 + tid + i * 256);
            cp_async16(d2 + i * 256 * 16, p2 + tid + i * 256);
        }
        cp_commit();
    }

    for (int s = s0; s < BC_; s += PGRID) {
        int nxt = s + PGRID;
        if (nxt < BC_) {
            const float4* p1 = (const float4*)(f1 + (size_t)nxt * HW_);
            const float4* p2 = (const float4*)(f2 + (size_t)nxt * HW_);
            uint32_t base = smem_base + (cur ^ 1) * (STAGE_FLOATS * 4);
            uint32_t d1 = base + tid * 16;
            uint32_t d2 = d1 + HW_ * 4;
            #pragma unroll
            for (int i = 0; i < 4; i++) {
                cp_async16(d1 + i * 256 * 16, p1 + tid + i * 256);
                cp_async16(d2 + i * 256 * 16, p2 + tid + i * 256);
            }
            cp_commit();
            cp_wait<1>();
        } else {
            cp_wait<0>();
        }
        __syncthreads();    // slice s fully in smem, visible to all

        const float* s1 = sm + cur * STAGE_FLOATS;
        const float* s2 = s1 + HW_;
        const int b = s >> 8;
        const int c = s & 255;

        // dot = sum(f1*f2) over the slice
        float dot = 0.0f;
        #pragma unroll
        for (int i = 0; i < 4; i++) {
            float4 a = ((const float4*)s1)[tid + i * 256];
            float4 d = ((const float4*)s2)[tid + i * 256];
            dot += a.x * d.x + a.y * d.y + a.z * d.z + a.w * d.w;
        }
        #pragma unroll
        for (int o = 16; o; o >>= 1) dot += __shfl_xor_sync(0xffffffffu, dot, o);
        if (lane == 0) red[warp] = dot;
        __syncthreads();
        if (tid == 0) {
            float t = 0.0f;
            #pragma unroll
            for (int i = 0; i < 8; i++) t += red[i];
            g_dot[s] = t;
        }

        // 42 rect sums (21 keypoints x 2 tensors), warp-per-rect.
        // Rect recomputed inline (broadcast load from pre, L1/L2-hot).
        for (int r = warp; r < 2 * K_; r += 8) {
            bool second = (r >= K_);
            int k = second ? (r - K_) : r;
            const float* p = second ? pre2 : pre1;
            float2 xy = __ldg((const float2*)(p + (b * K_ + k) * 2));
            int4 rc = make_rect(xy.x, xy.y);
            const float* ss = second ? s2 : s1;
            int nh = rc.y - rc.x;
            int nw = rc.w - rc.z;
            int base = rc.x * 64 + rc.z;
            float sum = 0.0f;
            bool wok = (dw < nw);
            if (wok && dh     < nh) sum += ss[base +  dh      * 64 + dw];
            if (wok && dh + 4 < nh) sum += ss[base + (dh + 4) * 64 + dw];
            #pragma unroll
            for (int o = 16; o; o >>= 1) sum += __shfl_xor_sync(0xffffffffu, sum, o);
            if (lane == 0) {
                float* dst = second ? g_S2 : g_S1;
                dst[((size_t)b * K_ + k) * C_ + c] = sum;
            }
        }
        __syncthreads();   // everyone done with buffer `cur` before it is reused
        cur ^= 1;
    }
}

// ---------------------------------------------------------------------------
// Kernel 2: partial accumulate over b. grid = (K_, NB_), block = 256 (c).
// ---------------------------------------------------------------------------
__global__ __launch_bounds__(256) void final_part_kernel(const float* __restrict__ pre1,
                                                         const float* __restrict__ pre2) {
    int k  = blockIdx.x;
    int by = blockIdx.y;
    int c  = threadIdx.x;
    int b0 = by * (B_ / NB_);
    float acc1 = 0.0f, acc2 = 0.0f;
    #pragma unroll
    for (int j = 0; j < B_ / NB_; j++) {
        int b = b0 + j;
        float2 xy1 = __ldg((const float2*)(pre1 + (b * K_ + k) * 2));
        float2 xy2 = __ldg((const float2*)(pre2 + (b * K_ + k) * 2));
        int4 r1 = make_rect(xy1.x, xy1.y);
        int4 r2 = make_rect(xy2.x, xy2.y);
        float i1 = 1.0f / (float)((r1.y - r1.x) * (r1.w - r1.z));
        float i2 = 1.0f / (float)((r2.y - r2.x) * (r2.w - r2.z));
        float d  = g_dot[b * C_ + c];
        size_t idx = ((size_t)b * K_ + k) * C_ + c;
        acc1 += d * g_S1[idx] * i1;
        acc2 += d * g_S2[idx] * i2;
    }
    int pidx = (k * NB_ + by) * C_ + c;
    g_part1[pidx] = acc1;
    g_part2[pidx] = acc2;
}

// ---------------------------------------------------------------------------
// Kernel 3: fused finale, single block of 1024 threads.
// max over g_dot; combine partials; EMA; mean of squared diff -> out[0].
// ---------------------------------------------------------------------------
__global__ __launch_bounds__(1024) void final_fused_kernel(const float* __restrict__ val1,
                                                           const float* __restrict__ val2,
                                                           float* __restrict__ out) {
    __shared__ float red[32];
    __shared__ float s_inv;
    const int tid = threadIdx.x;
    const int warp = tid >> 5, lane = tid & 31;

    // --- max over g_dot (16384) ---
    float m = -FLT_MAX;
    for (int i = tid; i < BC_; i += 1024) m = fmaxf(m, g_dot[i]);
    #pragma unroll
    for (int o = 16; o; o >>= 1) m = fmaxf(m, __shfl_xor_sync(0xffffffffu, m, o));
    if (lane == 0) red[warp] = m;
    __syncthreads();
    if (tid == 0) {
        float t = red[0];
        #pragma unroll
        for (int i = 1; i < 32; i++) t = fmaxf(t, red[i]);
        s_inv = 1.0f / ((float)B_ * t);
    }
    __syncthreads();
    float inv = s_inv;
    float v1 = __ldg(val1), v2 = __ldg(val2);

    // --- combine + EMA + squared diff, accumulate ---
    float acc_sq = 0.0f;
    for (int o = tid; o < KC_; o += 1024) {
        int k = o >> 8;       // C_ = 256
        int c = o & 255;
        float a1 = 0.0f, a2 = 0.0f;
        #pragma unroll
        for (int j = 0; j < NB_; j++) {
            int pidx = (k * NB_ + j) * C_ + c;
            a1 += g_part1[pidx];
            a2 += g_part2[pidx];
        }
        float fea1 = 0.999f * (a1 * inv) + 0.001f * v1;
        float fea2 = 0.999f * (a2 * inv) + 0.001f * v2;
        float df = fea1 - fea2;
        acc_sq += df * df;
    }
    __syncthreads();   // red[] reuse
    #pragma unroll
    for (int o = 16; o; o >>= 1) acc_sq += __shfl_xor_sync(0xffffffffu, acc_sq, o);
    if (lane == 0) red[warp] = acc_sq;
    __syncthreads();
    if (tid == 0) {
        float t = 0.0f;
        #pragma unroll
        for (int i = 0; i < 32; i++) t += red[i];
        out[0] = t / (float)KC_;
    }
}

extern "C" void kernel_launch(void* const* d_in, const int* in_sizes, int n_in,
                              void* d_out, int out_size) {
    const float* f1   = (const float*)d_in[0];
    const float* f2   = (const float*)d_in[1];
    const float* pre1 = (const float*)d_in[2];
    const float* pre2 = (const float*)d_in[3];
    const float* val1 = (const float*)d_in[4];
    const float* val2 = (const float*)d_in[5];
    float* out = (float*)d_out;

    // Unconditional (no static guards — harness contract). Deterministic,
    // not a stream op, no allocation; safe under graph capture.
    cudaFuncSetAttribute(pass1_kernel,
                         cudaFuncAttributeMaxDynamicSharedMemorySize, SMEM_BYTES);

    pass1_kernel<<<PGRID, 256, SMEM_BYTES>>>(f1, f2, pre1, pre2);
    final_part_kernel<<<dim3(K_, NB_), 256>>>(pre1, pre2);
    final_fused_kernel<<<1, 1024>>>(val1, val2, out);
}

// round 7
// speedup vs baseline: 1.1185x; 1.1185x over previous
#include <cuda_runtime.h>
#include <cstdint>
#include <math.h>
#include <float.h>

// Shapes
#define B_  64
#define C_  256
#define HW_ 4096        // 64*64
#define K_  21
#define BC_ (B_*C_)     // 16384
#define KC_ (K_*C_)     // 5376
#define NB_ 8           // b-groups for final partial stage

#define PGRID 444       // persistent grid (3 blocks/SM on 148 SMs)
#define NTHREADS 512
#define NWARPS 16
#define STAGE_FLOATS (2*HW_)           // s1 + s2 per stage = 8192 floats (32 KB)
#define SMEM_BYTES (2*STAGE_FLOATS*4)  // 2 stages = 64 KB

// Scratch (static device arrays — allowed)
__device__ float g_dot[BC_];
__device__ float g_S1[B_*K_*C_];
__device__ float g_S2[B_*K_*C_];
__device__ float g_part1[K_*NB_*C_];
__device__ float g_part2[K_*NB_*C_];

// Rect from keypoint (x,y): [left,right) x [down,upper), truncate after clip.
// Guaranteed 4 <= nh,nw <= 8.
__device__ __forceinline__ int4 make_rect(float x, float y) {
    int4 rc;
    rc.x = (int)fmaxf(x - 4.0f, 0.0f);   // left   (h)
    rc.y = (int)fminf(x + 4.0f, 63.0f);  // right  (h, excl)
    rc.z = (int)fmaxf(y - 4.0f, 0.0f);   // down   (w)
    rc.w = (int)fminf(y + 4.0f, 63.0f);  // upper  (w, excl)
    return rc;
}

// ---- cp.async helpers -----------------------------------------------------
__device__ __forceinline__ void cp_async16(uint32_t saddr, const void* g) {
    asm volatile("cp.async.cg.shared.global [%0], [%1], 16;" :: "r"(saddr), "l"(g));
}
__device__ __forceinline__ void cp_commit() {
    asm volatile("cp.async.commit_group;" ::: "memory");
}
template<int N> __device__ __forceinline__ void cp_wait() {
    asm volatile("cp.async.wait_group %0;" :: "n"(N) : "memory");
}

// ---------------------------------------------------------------------------
// Kernel 1: persistent, double-buffered streaming pass, 512 threads.
// 3 blocks/SM x 16 warps = 48 warps/SM (75% occ) — enough to hide the
// compute tail while cp.async keeps the next slice's loads in flight.
// ---------------------------------------------------------------------------
extern __shared__ float sm[];   // [2][8192]: per stage, s1 then s2

__global__ __launch_bounds__(NTHREADS) void pass1_kernel(const float* __restrict__ f1,
                                                         const float* __restrict__ f2,
                                                         const float* __restrict__ pre1,
                                                         const float* __restrict__ pre2) {
    __shared__ float red[NWARPS];
    const int tid  = threadIdx.x;
    const int warp = tid >> 5, lane = tid & 31;
    const int dh = lane >> 3;   // 0..3
    const int dw = lane & 7;    // 0..7
    const uint32_t smem_base = (uint32_t)__cvta_generic_to_shared(sm);

    int cur = 0;
    int s0 = blockIdx.x;

    // prologue: issue first slice (each thread: 2 float4 per tensor)
    {
        const float4* p1 = (const float4*)(f1 + (size_t)s0 * HW_);
        const float4* p2 = (const float4*)(f2 + (size_t)s0 * HW_);
        uint32_t d1 = smem_base + tid * 16;
        uint32_t d2 = d1 + HW_ * 4;
        #pragma unroll
        for (int i = 0; i < 2; i++) {
            cp_async16(d1 + i * NTHREADS * 16, p1 + tid + i * NTHREADS);
            cp_async16(d2 + i * NTHREADS * 16, p2 + tid + i * NTHREADS);
        }
        cp_commit();
    }

    for (int s = s0; s < BC_; s += PGRID) {
        int nxt = s + PGRID;
        if (nxt < BC_) {
            const float4* p1 = (const float4*)(f1 + (size_t)nxt * HW_);
            const float4* p2 = (const float4*)(f2 + (size_t)nxt * HW_);
            uint32_t base = smem_base + (cur ^ 1) * (STAGE_FLOATS * 4);
            uint32_t d1 = base + tid * 16;
            uint32_t d2 = d1 + HW_ * 4;
            #pragma unroll
            for (int i = 0; i < 2; i++) {
                cp_async16(d1 + i * NTHREADS * 16, p1 + tid + i * NTHREADS);
                cp_async16(d2 + i * NTHREADS * 16, p2 + tid + i * NTHREADS);
            }
            cp_commit();
            cp_wait<1>();
        } else {
            cp_wait<0>();
        }
        __syncthreads();    // slice s fully in smem, visible to all

        const float* s1 = sm + cur * STAGE_FLOATS;
        const float* s2 = s1 + HW_;
        const int b = s >> 8;
        const int c = s & 255;

        // dot = sum(f1*f2) over the slice (2 float4 per thread per tensor)
        float dot = 0.0f;
        #pragma unroll
        for (int i = 0; i < 2; i++) {
            float4 a = ((const float4*)s1)[tid + i * NTHREADS];
            float4 d = ((const float4*)s2)[tid + i * NTHREADS];
            dot += a.x * d.x + a.y * d.y + a.z * d.z + a.w * d.w;
        }
        #pragma unroll
        for (int o = 16; o; o >>= 1) dot += __shfl_xor_sync(0xffffffffu, dot, o);
        if (lane == 0) red[warp] = dot;
        __syncthreads();
        if (tid == 0) {
            float t = 0.0f;
            #pragma unroll
            for (int i = 0; i < NWARPS; i++) t += red[i];
            g_dot[s] = t;
        }

        // 42 rect sums (21 keypoints x 2 tensors), warp-per-rect (<=3 rounds).
        for (int r = warp; r < 2 * K_; r += NWARPS) {
            bool second = (r >= K_);
            int k = second ? (r - K_) : r;
            const float* p = second ? pre2 : pre1;
            float2 xy = __ldg((const float2*)(p + (b * K_ + k) * 2));
            int4 rc = make_rect(xy.x, xy.y);
            const float* ss = second ? s2 : s1;
            int nh = rc.y - rc.x;
            int nw = rc.w - rc.z;
            int base = rc.x * 64 + rc.z;
            float sum = 0.0f;
            bool wok = (dw < nw);
            if (wok && dh     < nh) sum += ss[base +  dh      * 64 + dw];
            if (wok && dh + 4 < nh) sum += ss[base + (dh + 4) * 64 + dw];
            #pragma unroll
            for (int o = 16; o; o >>= 1) sum += __shfl_xor_sync(0xffffffffu, sum, o);
            if (lane == 0) {
                float* dst = second ? g_S2 : g_S1;
                dst[((size_t)b * K_ + k) * C_ + c] = sum;
            }
        }
        __syncthreads();   // everyone done with buffer `cur` before reuse
        cur ^= 1;
    }
}

// ---------------------------------------------------------------------------
// Kernel 2: partial accumulate over b. grid = (K_, NB_), block = 256 (c).
// ---------------------------------------------------------------------------
__global__ __launch_bounds__(256) void final_part_kernel(const float* __restrict__ pre1,
                                                         const float* __restrict__ pre2) {
    int k  = blockIdx.x;
    int by = blockIdx.y;
    int c  = threadIdx.x;
    int b0 = by * (B_ / NB_);
    float acc1 = 0.0f, acc2 = 0.0f;
    #pragma unroll
    for (int j = 0; j < B_ / NB_; j++) {
        int b = b0 + j;
        float2 xy1 = __ldg((const float2*)(pre1 + (b * K_ + k) * 2));
        float2 xy2 = __ldg((const float2*)(pre2 + (b * K_ + k) * 2));
        int4 r1 = make_rect(xy1.x, xy1.y);
        int4 r2 = make_rect(xy2.x, xy2.y);
        float i1 = 1.0f / (float)((r1.y - r1.x) * (r1.w - r1.z));
        float i2 = 1.0f / (float)((r2.y - r2.x) * (r2.w - r2.z));
        float d  = g_dot[b * C_ + c];
        size_t idx = ((size_t)b * K_ + k) * C_ + c;
        acc1 += d * g_S1[idx] * i1;
        acc2 += d * g_S2[idx] * i2;
    }
    int pidx = (k * NB_ + by) * C_ + c;
    g_part1[pidx] = acc1;
    g_part2[pidx] = acc2;
}

// ---------------------------------------------------------------------------
// Kernel 3: fused finale, single block of 1024 threads.
// ---------------------------------------------------------------------------
__global__ __launch_bounds__(1024) void final_fused_kernel(const float* __restrict__ val1,
                                                           const float* __restrict__ val2,
                                                           float* __restrict__ out) {
    __shared__ float red[32];
    __shared__ float s_inv;
    const int tid = threadIdx.x;
    const int warp = tid >> 5, lane = tid & 31;

    // --- max over g_dot (16384) ---
    float m = -FLT_MAX;
    for (int i = tid; i < BC_; i += 1024) m = fmaxf(m, g_dot[i]);
    #pragma unroll
    for (int o = 16; o; o >>= 1) m = fmaxf(m, __shfl_xor_sync(0xffffffffu, m, o));
    if (lane == 0) red[warp] = m;
    __syncthreads();
    if (tid == 0) {
        float t = red[0];
        #pragma unroll
        for (int i = 1; i < 32; i++) t = fmaxf(t, red[i]);
        s_inv = 1.0f / ((float)B_ * t);
    }
    __syncthreads();
    float inv = s_inv;
    float v1 = __ldg(val1), v2 = __ldg(val2);

    // --- combine + EMA + squared diff, accumulate ---
    float acc_sq = 0.0f;
    for (int o = tid; o < KC_; o += 1024) {
        int k = o >> 8;       // C_ = 256
        int c = o & 255;
        float a1 = 0.0f, a2 = 0.0f;
        #pragma unroll
        for (int j = 0; j < NB_; j++) {
            int pidx = (k * NB_ + j) * C_ + c;
            a1 += g_part1[pidx];
            a2 += g_part2[pidx];
        }
        float fea1 = 0.999f * (a1 * inv) + 0.001f * v1;
        float fea2 = 0.999f * (a2 * inv) + 0.001f * v2;
        float df = fea1 - fea2;
        acc_sq += df * df;
    }
    __syncthreads();
    #pragma unroll
    for (int o = 16; o; o >>= 1) acc_sq += __shfl_xor_sync(0xffffffffu, acc_sq, o);
    if (lane == 0) red[warp] = acc_sq;
    __syncthreads();
    if (tid == 0) {
        float t = 0.0f;
        #pragma unroll
        for (int i = 0; i < 32; i++) t += red[i];
        out[0] = t / (float)KC_;
    }
}

extern "C" void kernel_launch(void* const* d_in, const int* in_sizes, int n_in,
                              void* d_out, int out_size) {
    const float* f1   = (const float*)d_in[0];
    const float* f2   = (const float*)d_in[1];
    const float* pre1 = (const float*)d_in[2];
    const float* pre2 = (const float*)d_in[3];
    const float* val1 = (const float*)d_in[4];
    const float* val2 = (const float*)d_in[5];
    float* out = (float*)d_out;

    cudaFuncSetAttribute(pass1_kernel,
                         cudaFuncAttributeMaxDynamicSharedMemorySize, SMEM_BYTES);

    pass1_kernel<<<PGRID, NTHREADS, SMEM_BYTES>>>(f1, f2, pre1, pre2);
    final_part_kernel<<<dim3(K_, NB_), 256>>>(pre1, pre2);
    final_fused_kernel<<<1, 1024>>>(val1, val2, out);
}

// round 8
// speedup vs baseline: 1.2347x; 1.1038x over previous
#include <cuda_runtime.h>
#include <cstdint>
#include <math.h>
#include <float.h>

// Shapes
#define B_  64
#define C_  256
#define HW_ 4096        // 64*64
#define K_  21
#define BC_ (B_*C_)     // 16384
#define KC_ (K_*C_)     // 5376
#define NB_ 8           // b-groups for final partial stage

#define PGRID 444       // persistent grid (3 blocks/SM on 148 SMs)
#define NTHREADS 512
#define NWARPS 16
#define STAGE_FLOATS (2*HW_)           // s1 + s2 per stage = 8192 floats (32 KB)
#define SMEM_BYTES (2*STAGE_FLOATS*4)  // 2 stages = 64 KB

// Scratch (static device arrays — allowed)
__device__ float g_dot[BC_];
__device__ float g_S1[B_*K_*C_];
__device__ float g_S2[B_*K_*C_];
__device__ float g_part1[K_*NB_*C_];
__device__ float g_part2[K_*NB_*C_];

// Rect from keypoint (x,y): [left,right) x [down,upper), truncate after clip.
// Guaranteed 4 <= nh,nw <= 8.
__device__ __forceinline__ int4 make_rect(float x, float y) {
    int4 rc;
    rc.x = (int)fmaxf(x - 4.0f, 0.0f);   // left   (h)
    rc.y = (int)fminf(x + 4.0f, 63.0f);  // right  (h, excl)
    rc.z = (int)fmaxf(y - 4.0f, 0.0f);   // down   (w)
    rc.w = (int)fminf(y + 4.0f, 63.0f);  // upper  (w, excl)
    return rc;
}

// ---- cp.async helpers -----------------------------------------------------
__device__ __forceinline__ void cp_async16(uint32_t saddr, const void* g) {
    asm volatile("cp.async.cg.shared.global [%0], [%1], 16;" :: "r"(saddr), "l"(g));
}
__device__ __forceinline__ void cp_commit() {
    asm volatile("cp.async.commit_group;" ::: "memory");
}
template<int N> __device__ __forceinline__ void cp_wait() {
    asm volatile("cp.async.wait_group %0;" :: "n"(N) : "memory");
}

// ---------------------------------------------------------------------------
// Kernel 1: persistent, double-buffered streaming pass, 512 threads.
// Contiguous-chunk slice assignment: each block handles ~37 consecutive
// (b,c) slices, so b changes at most twice per block. The 42 ROI rects
// (function of (b,k) only) are computed into smem ONCE per b — removing
// ~600 warp-insts/slice of setup that was choking the issue pipe in R7.
// ---------------------------------------------------------------------------
extern __shared__ float sm[];   // [2][8192]: per stage, s1 then s2

__global__ __launch_bounds__(NTHREADS) void pass1_kernel(const float* __restrict__ f1,
                                                         const float* __restrict__ f2,
                                                         const float* __restrict__ pre1,
                                                         const float* __restrict__ pre2) {
    __shared__ float red[NWARPS];
    __shared__ int4  s_rect[2 * K_];    // rects for current b (f1 then f2)
    const int tid  = threadIdx.x;
    const int warp = tid >> 5, lane = tid & 31;
    const int dh = lane >> 3;   // 0..3
    const int dw = lane & 7;    // 0..7
    const uint32_t smem_base = (uint32_t)__cvta_generic_to_shared(sm);

    // Contiguous chunk [gstart, gend) of slice indices g = b*256 + c
    const int gstart = (int)(((long long)blockIdx.x * BC_) / PGRID);
    const int gend   = (int)(((long long)(blockIdx.x + 1) * BC_) / PGRID);

    int cur = 0;
    int b_cur = -1;

    // prologue: issue first slice (each thread: 2 float4 per tensor)
    {
        const float4* p1 = (const float4*)(f1 + (size_t)gstart * HW_);
        const float4* p2 = (const float4*)(f2 + (size_t)gstart * HW_);
        uint32_t d1 = smem_base + tid * 16;
        uint32_t d2 = d1 + HW_ * 4;
        #pragma unroll
        for (int i = 0; i < 2; i++) {
            cp_async16(d1 + i * NTHREADS * 16, p1 + tid + i * NTHREADS);
            cp_async16(d2 + i * NTHREADS * 16, p2 + tid + i * NTHREADS);
        }
        cp_commit();
    }

    for (int g = gstart; g < gend; ++g) {
        if (g + 1 < gend) {
            const float4* p1 = (const float4*)(f1 + (size_t)(g + 1) * HW_);
            const float4* p2 = (const float4*)(f2 + (size_t)(g + 1) * HW_);
            uint32_t base = smem_base + (cur ^ 1) * (STAGE_FLOATS * 4);
            uint32_t d1 = base + tid * 16;
            uint32_t d2 = d1 + HW_ * 4;
            #pragma unroll
            for (int i = 0; i < 2; i++) {
                cp_async16(d1 + i * NTHREADS * 16, p1 + tid + i * NTHREADS);
                cp_async16(d2 + i * NTHREADS * 16, p2 + tid + i * NTHREADS);
            }
            cp_commit();
            cp_wait<1>();
        } else {
            cp_wait<0>();
        }
        __syncthreads();    // slice g fully in smem, visible to all

        const int b = g >> 8;
        const int c = g & 255;

        // b changed (at most twice per block): recompute the 42 rects.
        // Ordering: prior slice's rect reads finished before the trailing
        // barrier; the mid barrier below orders these writes before reads.
        if (b != b_cur) {
            if (tid < 2 * K_) {
                bool second = (tid >= K_);
                int k = second ? (tid - K_) : tid;
                const float* p = second ? pre2 : pre1;
                float2 xy = __ldg((const float2*)(p + (b * K_ + k) * 2));
                s_rect[tid] = make_rect(xy.x, xy.y);
            }
            b_cur = b;
        }

        const float* s1 = sm + cur * STAGE_FLOATS;
        const float* s2 = s1 + HW_;

        // dot = sum(f1*f2) over the slice (2 float4 per thread per tensor)
        float dot = 0.0f;
        #pragma unroll
        for (int i = 0; i < 2; i++) {
            float4 a = ((const float4*)s1)[tid + i * NTHREADS];
            float4 d = ((const float4*)s2)[tid + i * NTHREADS];
            dot += a.x * d.x + a.y * d.y + a.z * d.z + a.w * d.w;
        }
        #pragma unroll
        for (int o = 16; o; o >>= 1) dot += __shfl_xor_sync(0xffffffffu, dot, o);
        if (lane == 0) red[warp] = dot;
        __syncthreads();    // red ready; also publishes s_rect
        if (tid == 0) {
            float t = 0.0f;
            #pragma unroll
            for (int i = 0; i < NWARPS; i++) t += red[i];
            g_dot[g] = t;
        }

        // 42 rect sums, warp-per-rect (<=3 rounds), rects from smem (broadcast).
        for (int r = warp; r < 2 * K_; r += NWARPS) {
            int4 rc = s_rect[r];
            const float* ss = (r >= K_) ? s2 : s1;
            int nh = rc.y - rc.x;
            int nw = rc.w - rc.z;
            int base = rc.x * 64 + rc.z;
            float sum = 0.0f;
            bool wok = (dw < nw);
            if (wok && dh     < nh) sum += ss[base +  dh      * 64 + dw];
            if (wok && dh + 4 < nh) sum += ss[base + (dh + 4) * 64 + dw];
            #pragma unroll
            for (int o = 16; o; o >>= 1) sum += __shfl_xor_sync(0xffffffffu, sum, o);
            if (lane == 0) {
                int k = (r >= K_) ? (r - K_) : r;
                float* dst = (r >= K_) ? g_S2 : g_S1;
                dst[((size_t)b * K_ + k) * C_ + c] = sum;
            }
        }
        __syncthreads();   // everyone done with buffer `cur` before reuse
        cur ^= 1;
    }
}

// ---------------------------------------------------------------------------
// Kernel 2: partial accumulate over b. grid = (K_, NB_), block = 256 (c).
// ---------------------------------------------------------------------------
__global__ __launch_bounds__(256) void final_part_kernel(const float* __restrict__ pre1,
                                                         const float* __restrict__ pre2) {
    int k  = blockIdx.x;
    int by = blockIdx.y;
    int c  = threadIdx.x;
    int b0 = by * (B_ / NB_);
    float acc1 = 0.0f, acc2 = 0.0f;
    #pragma unroll
    for (int j = 0; j < B_ / NB_; j++) {
        int b = b0 + j;
        float2 xy1 = __ldg((const float2*)(pre1 + (b * K_ + k) * 2));
        float2 xy2 = __ldg((const float2*)(pre2 + (b * K_ + k) * 2));
        int4 r1 = make_rect(xy1.x, xy1.y);
        int4 r2 = make_rect(xy2.x, xy2.y);
        float i1 = 1.0f / (float)((r1.y - r1.x) * (r1.w - r1.z));
        float i2 = 1.0f / (float)((r2.y - r2.x) * (r2.w - r2.z));
        float d  = g_dot[b * C_ + c];
        size_t idx = ((size_t)b * K_ + k) * C_ + c;
        acc1 += d * g_S1[idx] * i1;
        acc2 += d * g_S2[idx] * i2;
    }
    int pidx = (k * NB_ + by) * C_ + c;
    g_part1[pidx] = acc1;
    g_part2[pidx] = acc2;
}

// ---------------------------------------------------------------------------
// Kernel 3: fused finale, single block of 1024 threads.
// ---------------------------------------------------------------------------
__global__ __launch_bounds__(1024) void final_fused_kernel(const float* __restrict__ val1,
                                                           const float* __restrict__ val2,
                                                           float* __restrict__ out) {
    __shared__ float red[32];
    __shared__ float s_inv;
    const int tid = threadIdx.x;
    const int warp = tid >> 5, lane = tid & 31;

    // --- max over g_dot (16384) ---
    float m = -FLT_MAX;
    for (int i = tid; i < BC_; i += 1024) m = fmaxf(m, g_dot[i]);
    #pragma unroll
    for (int o = 16; o; o >>= 1) m = fmaxf(m, __shfl_xor_sync(0xffffffffu, m, o));
    if (lane == 0) red[warp] = m;
    __syncthreads();
    if (tid == 0) {
        float t = red[0];
        #pragma unroll
        for (int i = 1; i < 32; i++) t = fmaxf(t, red[i]);
        s_inv = 1.0f / ((float)B_ * t);
    }
    __syncthreads();
    float inv = s_inv;
    float v1 = __ldg(val1), v2 = __ldg(val2);

    // --- combine + EMA + squared diff, accumulate ---
    float acc_sq = 0.0f;
    for (int o = tid; o < KC_; o += 1024) {
        int k = o >> 8;       // C_ = 256
        int c = o & 255;
        float a1 = 0.0f, a2 = 0.0f;
        #pragma unroll
        for (int j = 0; j < NB_; j++) {
            int pidx = (k * NB_ + j) * C_ + c;
            a1 += g_part1[pidx];
            a2 += g_part2[pidx];
        }
        float fea1 = 0.999f * (a1 * inv) + 0.001f * v1;
        float fea2 = 0.999f * (a2 * inv) + 0.001f * v2;
        float df = fea1 - fea2;
        acc_sq += df * df;
    }
    __syncthreads();
    #pragma unroll
    for (int o = 16; o; o >>= 1) acc_sq += __shfl_xor_sync(0xffffffffu, acc_sq, o);
    if (lane == 0) red[warp] = acc_sq;
    __syncthreads();
    if (tid == 0) {
        float t = 0.0f;
        #pragma unroll
        for (int i = 0; i < 32; i++) t += red[i];
        out[0] = t / (float)KC_;
    }
}

extern "C" void kernel_launch(void* const* d_in, const int* in_sizes, int n_in,
                              void* d_out, int out_size) {
    const float* f1   = (const float*)d_in[0];
    const float* f2   = (const float*)d_in[1];
    const float* pre1 = (const float*)d_in[2];
    const float* pre2 = (const float*)d_in[3];
    const float* val1 = (const float*)d_in[4];
    const float* val2 = (const float*)d_in[5];
    float* out = (float*)d_out;

    cudaFuncSetAttribute(pass1_kernel,
                         cudaFuncAttributeMaxDynamicSharedMemorySize, SMEM_BYTES);

    pass1_kernel<<<PGRID, NTHREADS, SMEM_BYTES>>>(f1, f2, pre1, pre2);
    final_part_kernel<<<dim3(K_, NB_), 256>>>(pre1, pre2);
    final_fused_kernel<<<1, 1024>>>(val1, val2, out);
}

// round 9
// speedup vs baseline: 1.3483x; 1.0920x over previous
#include <cuda_runtime.h>
#include <cstdint>
#include <math.h>
#include <float.h>

// Shapes
#define B_  64
#define C_  256
#define HW_ 4096        // 64*64
#define K_  21
#define BC_ (B_*C_)     // 16384
#define KC_ (K_*C_)     // 5376
#define NB_ 8           // b-groups for final partial stage

#define PGRID 444      // persistent grid (3 blocks/SM on 148 SMs)
#define NTHREADS 512
#define NWARPS 16
#define STAGE_FLOATS (2*HW_)           // s1 + s2 per stage = 8192 floats (32 KB)
#define SMEM_BYTES (2*STAGE_FLOATS*4)  // 2 stages = 64 KB

// Scratch (static device arrays — allowed)
__device__ float g_dot[BC_];
__device__ float g_S1[B_*K_*C_];
__device__ float g_S2[B_*K_*C_];
__device__ float g_part1[K_*NB_*C_];
__device__ float g_part2[K_*NB_*C_];

// Rect from keypoint (x,y): [left,right) x [down,upper), truncate after clip.
// Guaranteed 4 <= nh,nw <= 8.
__device__ __forceinline__ int4 make_rect(float x, float y) {
    int4 rc;
    rc.x = (int)fmaxf(x - 4.0f, 0.0f);   // left   (h)
    rc.y = (int)fminf(x + 4.0f, 63.0f);  // right  (h, excl)
    rc.z = (int)fmaxf(y - 4.0f, 0.0f);   // down   (w)
    rc.w = (int)fminf(y + 4.0f, 63.0f);  // upper  (w, excl)
    return rc;
}

// ---- cp.async helpers -----------------------------------------------------
__device__ __forceinline__ void cp_async16(uint32_t saddr, const void* g) {
    asm volatile("cp.async.cg.shared.global [%0], [%1], 16;" :: "r"(saddr), "l"(g));
}
__device__ __forceinline__ void cp_commit() {
    asm volatile("cp.async.commit_group;" ::: "memory");
}
template<int N> __device__ __forceinline__ void cp_wait() {
    asm volatile("cp.async.wait_group %0;" :: "n"(N) : "memory");
}

// ---------------------------------------------------------------------------
// Kernel 1: persistent streaming pass, 512 threads, ONE barrier per slice.
//
// Per slice g:
//   cp_wait (own cp.async data)  -> dot partial on OWN words (no barrier needed)
//   __syncthreads                -> slice visible, red visible, prev reads done
//   issue cp.async for g+1       -> safe: old buffer's readers passed barrier
//   warp0: shuffle-sum red -> g_dot[g];  all warps: rect sums -> g_S1/g_S2
//
// Rects for the (<=2) b values in this block's contiguous chunk are
// precomputed before the loop; no in-loop s_rect writes.
// ---------------------------------------------------------------------------
extern __shared__ float sm[];   // [2][8192]: per stage, s1 then s2

__global__ __launch_bounds__(NTHREADS) void pass1_kernel(const float* __restrict__ f1,
                                                         const float* __restrict__ f2,
                                                         const float* __restrict__ pre1,
                                                         const float* __restrict__ pre2) {
    __shared__ float red[2][NWARPS];   // double-buffered per-warp dot partials
    __shared__ int4  s_rect[2][2 * K_];
    const int tid  = threadIdx.x;
    const int warp = tid >> 5, lane = tid & 31;
    const int dh = lane >> 3;   // 0..3
    const int dw = lane & 7;    // 0..7
    const uint32_t smem_base = (uint32_t)__cvta_generic_to_shared(sm);

    // Contiguous chunk [gstart, gend) of slice indices g = b*256 + c
    const int gstart = (int)(((long long)blockIdx.x * BC_) / PGRID);
    const int gend   = (int)(((long long)(blockIdx.x + 1) * BC_) / PGRID);
    const int b0     = gstart >> 8;
    const int nb     = ((gend - 1) >> 8) - b0 + 1;   // 1 or 2

    // Precompute rects for the <=2 b values in this chunk.
    if (tid < nb * 2 * K_) {
        int bb = tid / (2 * K_);        // 0 or 1 (const divisor)
        int r  = tid - bb * (2 * K_);
        bool second = (r >= K_);
        int k = second ? (r - K_) : r;
        const float* p = second ? pre2 : pre1;
        float2 xy = __ldg((const float2*)(p + ((b0 + bb) * K_ + k) * 2));
        s_rect[bb][r] = make_rect(xy.x, xy.y);
    }
    // No barrier needed here: first rect read happens after the first
    // in-loop __syncthreads.

    // prologue: issue first slice (each thread: 2 float4 per tensor)
    {
        const float4* p1 = (const float4*)(f1 + (size_t)gstart * HW_);
        const float4* p2 = (const float4*)(f2 + (size_t)gstart * HW_);
        uint32_t d1 = smem_base + tid * 16;
        uint32_t d2 = d1 + HW_ * 4;
        #pragma unroll
        for (int i = 0; i < 2; i++) {
            cp_async16(d1 + i * NTHREADS * 16, p1 + tid + i * NTHREADS);
            cp_async16(d2 + i * NTHREADS * 16, p2 + tid + i * NTHREADS);
        }
        cp_commit();
    }

    int cur = 0;
    for (int g = gstart; g < gend; ++g) {
        cp_wait<0>();   // this thread's copies of slice g are in smem

        const float* s1 = sm + cur * STAGE_FLOATS;
        const float* s2 = s1 + HW_;

        // dot partial on OWN data (written by this thread's cp.async)
        float dot = 0.0f;
        #pragma unroll
        for (int i = 0; i < 2; i++) {
            float4 a = ((const float4*)s1)[tid + i * NTHREADS];
            float4 d = ((const float4*)s2)[tid + i * NTHREADS];
            dot += a.x * d.x + a.y * d.y + a.z * d.z + a.w * d.w;
        }
        #pragma unroll
        for (int o = 16; o; o >>= 1) dot += __shfl_xor_sync(0xffffffffu, dot, o);
        if (lane == 0) red[cur][warp] = dot;

        __syncthreads();   // slice g + red visible; prev buffer reads done

        // issue next slice into the buffer whose readers just passed the barrier
        if (g + 1 < gend) {
            const float4* p1 = (const float4*)(f1 + (size_t)(g + 1) * HW_);
            const float4* p2 = (const float4*)(f2 + (size_t)(g + 1) * HW_);
            uint32_t base = smem_base + (cur ^ 1) * (STAGE_FLOATS * 4);
            uint32_t d1 = base + tid * 16;
            uint32_t d2 = d1 + HW_ * 4;
            #pragma unroll
            for (int i = 0; i < 2; i++) {
                cp_async16(d1 + i * NTHREADS * 16, p1 + tid + i * NTHREADS);
                cp_async16(d2 + i * NTHREADS * 16, p2 + tid + i * NTHREADS);
            }
            cp_commit();
        }

        // warp 0: parallel sum of the 16 partials -> g_dot[g]
        if (warp == 0) {
            float t = (lane < NWARPS) ? red[cur][lane] : 0.0f;
            #pragma unroll
            for (int o = 8; o; o >>= 1) t += __shfl_xor_sync(0xffffffffu, t, o);
            if (lane == 0) g_dot[g] = t;
        }

        // 42 rect sums, warp-per-rect. Reverse warp order so warp 0 (which
        // also did the red sum) gets the 2-rect share.
        const int b   = g >> 8;
        const int c   = g & 255;
        const int4* rects = s_rect[b - b0];
        for (int r = (NWARPS - 1 - warp); r < 2 * K_; r += NWARPS) {
            int4 rc = rects[r];
            const float* ss = (r >= K_) ? s2 : s1;
            int nh = rc.y - rc.x;
            int nw = rc.w - rc.z;
            int base = rc.x * 64 + rc.z;
            float sum = 0.0f;
            bool wok = (dw < nw);
            if (wok && dh     < nh) sum += ss[base +  dh      * 64 + dw];
            if (wok && dh + 4 < nh) sum += ss[base + (dh + 4) * 64 + dw];
            #pragma unroll
            for (int o = 16; o; o >>= 1) sum += __shfl_xor_sync(0xffffffffu, sum, o);
            if (lane == 0) {
                int k = (r >= K_) ? (r - K_) : r;
                float* dst = (r >= K_) ? g_S2 : g_S1;
                dst[((size_t)b * K_ + k) * C_ + c] = sum;
            }
        }
        cur ^= 1;
    }
}

// ---------------------------------------------------------------------------
// Kernel 2: partial accumulate over b. grid = (K_, NB_), block = 256 (c).
// ---------------------------------------------------------------------------
__global__ __launch_bounds__(256) void final_part_kernel(const float* __restrict__ pre1,
                                                         const float* __restrict__ pre2) {
    int k  = blockIdx.x;
    int by = blockIdx.y;
    int c  = threadIdx.x;
    int b0 = by * (B_ / NB_);
    float acc1 = 0.0f, acc2 = 0.0f;
    #pragma unroll
    for (int j = 0; j < B_ / NB_; j++) {
        int b = b0 + j;
        float2 xy1 = __ldg((const float2*)(pre1 + (b * K_ + k) * 2));
        float2 xy2 = __ldg((const float2*)(pre2 + (b * K_ + k) * 2));
        int4 r1 = make_rect(xy1.x, xy1.y);
        int4 r2 = make_rect(xy2.x, xy2.y);
        float i1 = 1.0f / (float)((r1.y - r1.x) * (r1.w - r1.z));
        float i2 = 1.0f / (float)((r2.y - r2.x) * (r2.w - r2.z));
        float d  = g_dot[b * C_ + c];
        size_t idx = ((size_t)b * K_ + k) * C_ + c;
        acc1 += d * g_S1[idx] * i1;
        acc2 += d * g_S2[idx] * i2;
    }
    int pidx = (k * NB_ + by) * C_ + c;
    g_part1[pidx] = acc1;
    g_part2[pidx] = acc2;
}

// ---------------------------------------------------------------------------
// Kernel 3: fused finale, single block of 1024 threads.
// ---------------------------------------------------------------------------
__global__ __launch_bounds__(1024) void final_fused_kernel(const float* __restrict__ val1,
                                                           const float* __restrict__ val2,
                                                           float* __restrict__ out) {
    __shared__ float red[32];
    __shared__ float s_inv;
    const int tid = threadIdx.x;
    const int warp = tid >> 5, lane = tid & 31;

    // --- max over g_dot (16384) ---
    float m = -FLT_MAX;
    for (int i = tid; i < BC_; i += 1024) m = fmaxf(m, g_dot[i]);
    #pragma unroll
    for (int o = 16; o; o >>= 1) m = fmaxf(m, __shfl_xor_sync(0xffffffffu, m, o));
    if (lane == 0) red[warp] = m;
    __syncthreads();
    if (tid == 0) {
        float t = red[0];
        #pragma unroll
        for (int i = 1; i < 32; i++) t = fmaxf(t, red[i]);
        s_inv = 1.0f / ((float)B_ * t);
    }
    __syncthreads();
    float inv = s_inv;
    float v1 = __ldg(val1), v2 = __ldg(val2);

    // --- combine + EMA + squared diff, accumulate ---
    float acc_sq = 0.0f;
    for (int o = tid; o < KC_; o += 1024) {
        int k = o >> 8;       // C_ = 256
        int c = o & 255;
        float a1 = 0.0f, a2 = 0.0f;
        #pragma unroll
        for (int j = 0; j < NB_; j++) {
            int pidx = (k * NB_ + j) * C_ + c;
            a1 += g_part1[pidx];
            a2 += g_part2[pidx];
        }
        float fea1 = 0.999f * (a1 * inv) + 0.001f * v1;
        float fea2 = 0.999f * (a2 * inv) + 0.001f * v2;
        float df = fea1 - fea2;
        acc_sq += df * df;
    }
    __syncthreads();
    #pragma unroll
    for (int o = 16; o; o >>= 1) acc_sq += __shfl_xor_sync(0xffffffffu, acc_sq, o);
    if (lane == 0) red[warp] = acc_sq;
    __syncthreads();
    if (tid == 0) {
        float t = 0.0f;
        #pragma unroll
        for (int i = 0; i < 32; i++) t += red[i];
        out[0] = t / (float)KC_;
    }
}

extern "C" void kernel_launch(void* const* d_in, const int* in_sizes, int n_in,
                              void* d_out, int out_size) {
    const float* f1   = (const float*)d_in[0];
    const float* f2   = (const float*)d_in[1];
    const float* pre1 = (const float*)d_in[2];
    const float* pre2 = (const float*)d_in[3];
    const float* val1 = (const float*)d_in[4];
    const float* val2 = (const float*)d_in[5];
    float* out = (float*)d_out;

    cudaFuncSetAttribute(pass1_kernel,
                         cudaFuncAttributeMaxDynamicSharedMemorySize, SMEM_BYTES);

    pass1_kernel<<<PGRID, NTHREADS, SMEM_BYTES>>>(f1, f2, pre1, pre2);
    final_part_kernel<<<dim3(K_, NB_), 256>>>(pre1, pre2);
    final_fused_kernel<<<1, 1024>>>(val1, val2, out);
}